// round 15
// baseline (speedup 1.0000x reference)
#include <cuda_runtime.h>
#include <cuda_bf16.h>
#include <cuda_fp16.h>
#include <cstdint>
#include <math.h>

#define BATCH 16
#define CH    256
#define NPIX  4096
#define DQH   64
#define SST   72     // SMEM row stride in elements (144B): conflict-free ldmatrix
#define EST   136    // E-tile SMEM row stride: conflict-free ldmatrix(.trans)
#define NSTEP (NPIX / 64)
#define JSPLIT 2
#define NSTEP2 (NSTEP / JSPLIT)
#define EXPOFF 36.0f

// ===========================================================================
// Scratch (device globals)
// ===========================================================================
__device__ __nv_bfloat16 g_qh[BATCH * NPIX * DQH];
__device__ __nv_bfloat16 g_ql[BATCH * NPIX * DQH];
__device__ __nv_bfloat16 g_kh[BATCH * NPIX * DQH];
__device__ __nv_bfloat16 g_kl[BATCH * NPIX * DQH];
__device__ __half        g_v [BATCH * CH * NPIX];           // [b][c][j] V^T fp16
__device__ __half        g_e [(size_t)BATCH * NPIX * NPIX]; // E[b][j][i] = exp(S - m_loc)
__device__ float g_scl[(size_t)BATCH * NSTEP * NPIX];       // [b][iblk][j] exp(m_loc-36)
__device__ float g_z  [BATCH * NPIX];                       // 1/Z fp32

__device__ __forceinline__ void split_bf16(float v, __nv_bfloat16& h, __nv_bfloat16& l) {
    h = __float2bfloat16_rn(v);
    l = __float2bfloat16_rn(v - __bfloat162float(h));
}

__device__ __forceinline__ void mma_bf(float c[4],
    const uint32_t a[4], uint32_t b0, uint32_t b1)
{
    asm volatile(
        "mma.sync.aligned.m16n8k16.row.col.f32.bf16.bf16.f32 "
        "{%0,%1,%2,%3},{%4,%5,%6,%7},{%8,%9},{%0,%1,%2,%3};"
        : "+f"(c[0]), "+f"(c[1]), "+f"(c[2]), "+f"(c[3])
        : "r"(a[0]), "r"(a[1]), "r"(a[2]), "r"(a[3]), "r"(b0), "r"(b1));
}
__device__ __forceinline__ void mma_fp(float c[4],
    const uint32_t a[4], uint32_t b0, uint32_t b1)
{
    asm volatile(
        "mma.sync.aligned.m16n8k16.row.col.f32.f16.f16.f32 "
        "{%0,%1,%2,%3},{%4,%5,%6,%7},{%8,%9},{%0,%1,%2,%3};"
        : "+f"(c[0]), "+f"(c[1]), "+f"(c[2]), "+f"(c[3])
        : "r"(a[0]), "r"(a[1]), "r"(a[2]), "r"(a[3]), "r"(b0), "r"(b1));
}
__device__ __forceinline__ void ldsm4(uint32_t r[4], uint32_t addr) {
    asm volatile("ldmatrix.sync.aligned.m8n8.x4.shared.b16 {%0,%1,%2,%3}, [%4];"
        : "=r"(r[0]), "=r"(r[1]), "=r"(r[2]), "=r"(r[3]) : "r"(addr));
}
__device__ __forceinline__ void ldsm4t(uint32_t r[4], uint32_t addr) {
    asm volatile("ldmatrix.sync.aligned.m8n8.x4.trans.shared.b16 {%0,%1,%2,%3}, [%4];"
        : "=r"(r[0]), "=r"(r[1]), "=r"(r[2]), "=r"(r[3]) : "r"(addr));
}
__device__ __forceinline__ uint32_t cvta_s(const void* p) {
    return (uint32_t)__cvta_generic_to_shared(p);
}
__device__ __forceinline__ void cpa16(uint32_t dst, const void* src) {
    asm volatile("cp.async.cg.shared.global [%0], [%1], 16;" :: "r"(dst), "l"(src));
}
__device__ __forceinline__ void stg_cs32(void* p, uint32_t v) {
    asm volatile("st.global.cs.u32 [%0], %1;" :: "l"(p), "r"(v));
}
#define CP_COMMIT() asm volatile("cp.async.commit_group;" ::: "memory")
#define CP_WAIT0()  asm volatile("cp.async.wait_group 0;" ::: "memory")
#define CP_WAIT1()  asm volatile("cp.async.wait_group 1;" ::: "memory")

__device__ __forceinline__ uint32_t a_off(int m0, int lane) {
    return ((m0 + (lane & 15)) * SST + ((lane >> 4) << 3)) * 2;
}
__device__ __forceinline__ uint32_t b_off(int n0, int lane) {
    return ((n0 + ((lane >> 4) << 3) + (lane & 7)) * SST + (((lane >> 3) & 1) << 3)) * 2;
}
__device__ __forceinline__ uint32_t eat_off(int k0, int m0, int lane) {
    return ((k0 + (lane & 7) + ((lane >> 4) << 3)) * EST
            + m0 + (((lane >> 3) & 1) << 3)) * 2;
}

// ===========================================================================
__global__ void zero_out_kernel(float4* __restrict__ p) {
    size_t base = (size_t)blockIdx.x * 1024 + threadIdx.x;
#pragma unroll
    for (int k = 0; k < 4; k++) p[base + k * 256] = make_float4(0.f, 0.f, 0.f, 0.f);
}

// ===========================================================================
// Unified projection: blockIdx.y = 0 (Q), 1 (K), 2..5 (V d-tile y-2).
// ===========================================================================
#define PXST 136
#define PWST 264
#define PXH  0
#define PXL  (256 * PXST * 2)
#define PWH  (2 * 256 * PXST * 2)
#define PWL  (PWH + 64 * PWST * 2)
#define PSMEM (PWL + 64 * PWST * 2)

__device__ __forceinline__ uint32_t at_off(int k0, int m0, int lane) {
    return ((k0 + (lane & 7) + ((lane >> 4) << 3)) * PXST
            + m0 + (((lane >> 3) & 1) << 3)) * 2;
}
__device__ __forceinline__ uint32_t bW_off(int n0, int k0, int lane) {
    return ((n0 + ((lane >> 4) << 3) + (lane & 7)) * PWST
            + k0 + (((lane >> 3) & 1) << 3)) * 2;
}

__device__ __forceinline__ void proj_load_x(
    char* smp, const float* __restrict__ Xb, int tid)
{
#pragma unroll 4
    for (int t = 0; t < 32; t++) {
        int e = tid + t * 256;
        int c = e >> 5, q = (e & 31) * 4;
        float4 x = *(const float4*)&Xb[(size_t)c * NPIX + q];
        __nv_bfloat16 h[4], l[4];
        split_bf16(x.x, h[0], l[0]);
        split_bf16(x.y, h[1], l[1]);
        split_bf16(x.z, h[2], l[2]);
        split_bf16(x.w, h[3], l[3]);
        *(uint2*)(smp + PXH + (c * PXST + q) * 2) = *(uint2*)h;
        *(uint2*)(smp + PXL + (c * PXST + q) * 2) = *(uint2*)l;
    }
}
__device__ __forceinline__ void proj_load_w(
    char* smp, const float* __restrict__ Wd, int tid)
{
#pragma unroll 4
    for (int t = 0; t < 16; t++) {
        int e = tid + t * 256;
        int r = e >> 6, q = (e & 63) * 4;
        float4 w = *(const float4*)&Wd[(size_t)r * CH + q];
        __nv_bfloat16 h[4], l[4];
        split_bf16(w.x, h[0], l[0]);
        split_bf16(w.y, h[1], l[1]);
        split_bf16(w.z, h[2], l[2]);
        split_bf16(w.w, h[3], l[3]);
        *(uint2*)(smp + PWH + (r * PWST + q) * 2) = *(uint2*)h;
        *(uint2*)(smp + PWL + (r * PWST + q) * 2) = *(uint2*)l;
    }
}
__device__ __forceinline__ void proj_core(
    char* smp, uint32_t sb, float o[8][4], int m0, int lane)
{
#pragma unroll
    for (int ks = 0; ks < 16; ks++) {
        const int k0 = ks * 16;
        uint32_t ah[4], al[4];
        ldsm4t(ah, sb + PXH + at_off(k0, m0, lane));
        ldsm4t(al, sb + PXL + at_off(k0, m0, lane));
#pragma unroll
        for (int g = 0; g < 4; g++) {
            uint32_t bh[4], bl[4];
            ldsm4(bh, sb + PWH + bW_off(g * 16, k0, lane));
            ldsm4(bl, sb + PWL + bW_off(g * 16, k0, lane));
            mma_bf(o[2*g],   ah, bh[0], bh[1]);
            mma_bf(o[2*g+1], ah, bh[2], bh[3]);
            mma_bf(o[2*g],   ah, bl[0], bl[1]);
            mma_bf(o[2*g+1], ah, bl[2], bl[3]);
            mma_bf(o[2*g],   al, bh[0], bh[1]);
            mma_bf(o[2*g+1], al, bh[2], bh[3]);
        }
    }
}

__global__ void __launch_bounds__(256) proj_all_mma(
    const float* __restrict__ Xq, const float* __restrict__ Xk,
    const float* __restrict__ Xv,
    const float* __restrict__ Wq, const float* __restrict__ Wk,
    const float* __restrict__ Wv,
    const float* __restrict__ bq, const float* __restrict__ bk,
    const float* __restrict__ bv,
    __nv_bfloat16* __restrict__ qh, __nv_bfloat16* __restrict__ ql,
    __nv_bfloat16* __restrict__ kh, __nv_bfloat16* __restrict__ kl,
    __half* __restrict__ ov)
{
    extern __shared__ char smp[];
    const uint32_t sb = cvta_s(smp);
    const int b = blockIdx.z, j0 = blockIdx.x * 128, which = blockIdx.y;
    const int tid = threadIdx.x, warp = tid >> 5, lane = tid & 31;
    const int m0 = warp * 16;

    if (which < 2) {
        const float* X = which ? Xk : Xq;
        const float* W = which ? Wk : Wq;
        const float* bias = which ? bk : bq;
        __nv_bfloat16* oh = which ? kh : qh;
        __nv_bfloat16* ol = which ? kl : ql;

        proj_load_x(smp, X + (size_t)b * CH * NPIX + j0, tid);
        proj_load_w(smp, W, tid);
        __syncthreads();

        float o[8][4] = {};
        proj_core(smp, sb, o, m0, lane);

        const int r = m0 + (lane >> 2);
#pragma unroll
        for (int nt = 0; nt < 8; nt++) {
            const int d = nt * 8 + 2 * (lane & 3);
            const float b0 = bias[d], b1 = bias[d + 1];
            __nv_bfloat162 h, l;
            split_bf16(o[nt][0] + b0, h.x, l.x);
            split_bf16(o[nt][1] + b1, h.y, l.y);
            size_t base = ((size_t)b * NPIX + j0 + r) * DQH + d;
            *(uint32_t*)&oh[base] = *(uint32_t*)&h;
            *(uint32_t*)&ol[base] = *(uint32_t*)&l;
            split_bf16(o[nt][2] + b0, h.x, l.x);
            split_bf16(o[nt][3] + b1, h.y, l.y);
            base = ((size_t)b * NPIX + j0 + r + 8) * DQH + d;
            *(uint32_t*)&oh[base] = *(uint32_t*)&h;
            *(uint32_t*)&ol[base] = *(uint32_t*)&l;
        }
    } else {
        const int dt = which - 2;
        proj_load_x(smp, Xv + (size_t)b * CH * NPIX + j0, tid);
        proj_load_w(smp, Wv + (size_t)(dt * 64) * CH, tid);
        __syncthreads();

        float o[8][4] = {};
        proj_core(smp, sb, o, m0, lane);

        const int r = m0 + (lane >> 2);
        __syncthreads();
#pragma unroll
        for (int nt = 0; nt < 8; nt++) {
            const int d = nt * 8 + 2 * (lane & 3);
            const float b0 = bv[dt * 64 + d], b1 = bv[dt * 64 + d + 1];
            *(__half*)(smp + PWH + ((d)     * PXST + r)     * 2) = __float2half_rn(o[nt][0] + b0);
            *(__half*)(smp + PWH + ((d + 1) * PXST + r)     * 2) = __float2half_rn(o[nt][1] + b1);
            *(__half*)(smp + PWH + ((d)     * PXST + r + 8) * 2) = __float2half_rn(o[nt][2] + b0);
            *(__half*)(smp + PWH + ((d + 1) * PXST + r + 8) * 2) = __float2half_rn(o[nt][3] + b1);
        }
        __syncthreads();
#pragma unroll
        for (int t = 0; t < 4; t++) {
            int e = tid + t * 256;
            int dr = e >> 4, q = (e & 15) * 8;
            uint4 val = *(uint4*)(smp + PWH + (dr * PXST + q) * 2);
            *(uint4*)&ov[((size_t)b * CH + dt * 64 + dr) * NPIX + j0 + q] = val;
        }
    }
}

// ===========================================================================
// Pass A: S once (bf16x3); per (row, 64-i-block) local max; E fp16, scl fp32,
// Z fp32 exact.
// ===========================================================================
#define RS_STG 18432
#define RS_SMEM (3 * RS_STG)

__global__ void __launch_bounds__(256, 2) rowstats_mma(
    const __nv_bfloat16* __restrict__ gqh, const __nv_bfloat16* __restrict__ gql,
    const __nv_bfloat16* __restrict__ gkh, const __nv_bfloat16* __restrict__ gkl,
    __half* __restrict__ ge, float* __restrict__ gscl, float* __restrict__ gz)
{
    extern __shared__ char sma[];
    const uint32_t sb = cvta_s(sma);
    const int b = blockIdx.y, j0 = blockIdx.x * 128;
    const int tid = threadIdx.x, warp = tid >> 5, lane = tid & 31;
    const int m0 = warp * 16;

    {
        const __nv_bfloat16* ph = gqh + ((size_t)b * NPIX + j0) * DQH;
        const __nv_bfloat16* pl = gql + ((size_t)b * NPIX + j0) * DQH;
#pragma unroll
        for (int t = 0; t < 4; t++) {
            int e = tid + t * 256, r = e >> 3, c8 = e & 7;
            int hb = r >> 6, rl = r & 63;
            cpa16(sb + hb * RS_STG + (rl * SST + c8 * 8) * 2, ph + (size_t)r * DQH + c8 * 8);
            cpa16(sb + hb * RS_STG + 9216 + (rl * SST + c8 * 8) * 2, pl + (size_t)r * DQH + c8 * 8);
        }
        CP_COMMIT(); CP_WAIT0();
        __syncthreads();
    }
    uint32_t qah[4][4], qal[4][4];
    {
        const uint32_t base = sb + (m0 >> 6) * RS_STG;
        const uint32_t ao = a_off(m0 & 63, lane);
#pragma unroll
        for (int ks = 0; ks < 4; ks++) {
            ldsm4(qah[ks], base + ao + ks * 32);
            ldsm4(qal[ks], base + 9216 + ao + ks * 32);
        }
    }
    __syncthreads();

    auto issue_k = [&](int step, int s) {
        const __nv_bfloat16* ph = gkh + ((size_t)b * NPIX + step * 64) * DQH;
        const __nv_bfloat16* pl = gkl + ((size_t)b * NPIX + step * 64) * DQH;
#pragma unroll
        for (int t = 0; t < 2; t++) {
            int e = tid + t * 256, r = e >> 3, c8 = e & 7;
            cpa16(sb + s * RS_STG + (r * SST + c8 * 8) * 2, ph + (size_t)r * DQH + c8 * 8);
            cpa16(sb + s * RS_STG + 9216 + (r * SST + c8 * 8) * 2, pl + (size_t)r * DQH + c8 * 8);
        }
        CP_COMMIT();
    };
    issue_k(0, 0);
    issue_k(1, 1);

    float z0 = 0.f, z1 = 0.f;
    const uint32_t bo_b = b_off(0, lane);
    const int r0 = m0 + (lane >> 2), r1 = r0 + 8;
    __half* e0base = ge + ((size_t)b * NPIX + j0 + r0) * NPIX + 2 * (lane & 3);
    __half* e1base = ge + ((size_t)b * NPIX + j0 + r1) * NPIX + 2 * (lane & 3);

    for (int t = 0; t < NSTEP; t++) {
        CP_WAIT1();
        __syncthreads();
        issue_k((t + 2) % NSTEP, (t + 2) % 3);

        const uint32_t kh = sb + (t % 3) * RS_STG;
        const uint32_t kl = kh + 9216;
        float sacc[8][4] = {};
#pragma unroll
        for (int g = 0; g < 4; g++) {
            const uint32_t bog = bo_b + g * (16 * SST * 2);
#pragma unroll
            for (int ks = 0; ks < 4; ks++) {
                const uint32_t bo = bog + ks * 32;
                uint32_t bh[4], bl[4];
                ldsm4(bh, kh + bo);
                ldsm4(bl, kl + bo);
                mma_bf(sacc[2*g],   qah[ks], bh[0], bh[1]);
                mma_bf(sacc[2*g+1], qah[ks], bh[2], bh[3]);
                mma_bf(sacc[2*g],   qah[ks], bl[0], bl[1]);
                mma_bf(sacc[2*g+1], qah[ks], bl[2], bl[3]);
                mma_bf(sacc[2*g],   qal[ks], bh[0], bh[1]);
                mma_bf(sacc[2*g+1], qal[ks], bh[2], bh[3]);
            }
        }

        float m0v = -1e30f, m1v = -1e30f;
#pragma unroll
        for (int nt = 0; nt < 8; nt++) {
            m0v = fmaxf(m0v, fmaxf(sacc[nt][0], sacc[nt][1]));
            m1v = fmaxf(m1v, fmaxf(sacc[nt][2], sacc[nt][3]));
        }
        m0v = fmaxf(m0v, __shfl_xor_sync(0xffffffffu, m0v, 1));
        m0v = fmaxf(m0v, __shfl_xor_sync(0xffffffffu, m0v, 2));
        m1v = fmaxf(m1v, __shfl_xor_sync(0xffffffffu, m1v, 1));
        m1v = fmaxf(m1v, __shfl_xor_sync(0xffffffffu, m1v, 2));
        const float scl0 = __expf(m0v - EXPOFF);
        const float scl1 = __expf(m1v - EXPOFF);

        __half* e0p = e0base + t * 64;
        __half* e1p = e1base + t * 64;
        float zs0 = 0.f, zs1 = 0.f;
#pragma unroll
        for (int g = 0; g < 4; g++) {
            float e0 = __expf(sacc[2*g][0]   - m0v);
            float e1 = __expf(sacc[2*g][1]   - m0v);
            float e2 = __expf(sacc[2*g][2]   - m1v);
            float e3 = __expf(sacc[2*g][3]   - m1v);
            float e4 = __expf(sacc[2*g+1][0] - m0v);
            float e5 = __expf(sacc[2*g+1][1] - m0v);
            float e6 = __expf(sacc[2*g+1][2] - m1v);
            float e7 = __expf(sacc[2*g+1][3] - m1v);
            zs0 += e0 + e1 + e4 + e5;
            zs1 += e2 + e3 + e6 + e7;
            __half2 h00 = __floats2half2_rn(e0, e1);
            __half2 h10 = __floats2half2_rn(e2, e3);
            __half2 h01 = __floats2half2_rn(e4, e5);
            __half2 h11 = __floats2half2_rn(e6, e7);
            stg_cs32(e0p + 16 * g,     *(uint32_t*)&h00);
            stg_cs32(e1p + 16 * g,     *(uint32_t*)&h10);
            stg_cs32(e0p + 16 * g + 8, *(uint32_t*)&h01);
            stg_cs32(e1p + 16 * g + 8, *(uint32_t*)&h11);
        }
        z0 += zs0 * scl0;
        z1 += zs1 * scl1;
        if ((lane & 3) == 0) {
            float* sp = gscl + ((size_t)(b * NSTEP + t)) * NPIX + j0;
            sp[r0] = scl0;
            sp[r1] = scl1;
        }
    }

    z0 += __shfl_xor_sync(0xffffffffu, z0, 1);
    z0 += __shfl_xor_sync(0xffffffffu, z0, 2);
    z1 += __shfl_xor_sync(0xffffffffu, z1, 1);
    z1 += __shfl_xor_sync(0xffffffffu, z1, 2);
    if ((lane & 3) == 0) {
        gz[(size_t)b * NPIX + j0 + r0] = 1.0f / z0;
        gz[(size_t)b * NPIX + j0 + r1] = 1.0f / z1;
    }
}

// ===========================================================================
// Pass B (j-split x c-split): pure fp16 GEMM, 2 CTAs/SM.
// CTA = (i-tile 128, jhalf, chalf, batch). P = E * (scl*iz).
// ===========================================================================
#define AT_E_SZ  (64 * EST * 2)            // 17408
#define AT_V_SZ  (128 * SST * 2)           // 18432 (c-half)
#define AT_SC_SZ 768
#define AT_STG   (AT_E_SZ + AT_V_SZ + AT_SC_SZ)  // 36608
#define AT_E(s)  ((s) * AT_STG)
#define AT_V(s)  ((s) * AT_STG + AT_E_SZ)
#define AT_SC(s) ((s) * AT_STG + AT_E_SZ + AT_V_SZ)
#define AT_SMEM  (3 * AT_STG)              // 109824

__global__ void __launch_bounds__(256, 2) attn_mma(
    const __half* __restrict__ ge, const float* __restrict__ gscl,
    const float* __restrict__ gz, const __half* __restrict__ gv,
    float* __restrict__ out)
{
    extern __shared__ char smb[];
    const uint32_t sb = cvta_s(smb);
    const int b = blockIdx.z, i0 = blockIdx.x * 128;
    const int iblk0 = blockIdx.x * 2;
    const int jh = blockIdx.y >> 1, ch = blockIdx.y & 1;
    const int jbase = jh * NSTEP2;
    const int tid = threadIdx.x, warp = tid >> 5, lane = tid & 31;
    const int m0 = warp * 16;

    auto issue = [&](int step, int s) {
        const int gstep = jbase + step;
        const __half* pe = ge + ((size_t)b * NPIX + (size_t)gstep * 64) * NPIX + i0;
#pragma unroll
        for (int t = 0; t < 4; t++) {
            int e = tid + t * 256, r = e >> 4, c8 = e & 15;
            cpa16(sb + AT_E(s) + (r * EST + c8 * 8) * 2, pe + (size_t)r * NPIX + c8 * 8);
        }
        const __half* pv = gv + (size_t)b * CH * NPIX + (size_t)(ch * 128) * NPIX + gstep * 64;
#pragma unroll
        for (int t = 0; t < 4; t++) {
            int e = tid + t * 256, r = e >> 3, c8 = e & 7;
            cpa16(sb + AT_V(s) + (r * SST + c8 * 8) * 2, pv + (size_t)r * NPIX + c8 * 8);
        }
        if (tid < 16)
            cpa16(sb + AT_SC(s) + tid * 16,
                  gscl + ((size_t)(b * NSTEP + iblk0)) * NPIX + gstep * 64 + tid * 4);
        else if (tid < 32)
            cpa16(sb + AT_SC(s) + 256 + (tid - 16) * 16,
                  gscl + ((size_t)(b * NSTEP + iblk0 + 1)) * NPIX + gstep * 64 + (tid - 16) * 4);
        else if (tid < 48)
            cpa16(sb + AT_SC(s) + 512 + (tid - 32) * 16,
                  gz + (size_t)b * NPIX + gstep * 64 + (tid - 32) * 4);
        CP_COMMIT();
    };
    issue(0, 0);
    issue(1, 1);

    float o[16][4] = {};
    const uint32_t bo_b = b_off(0, lane);

    for (int t = 0; t < NSTEP2; t++) {
        CP_WAIT1();
        __syncthreads();
        issue((t + 2) % NSTEP2, (t + 2) % 3);

        const int s = t % 3;
        const uint32_t esm = sb + AT_E(s), vv = sb + AT_V(s);
        const float* sclp = (const float*)(smb + AT_SC(s)) + ((m0 >= 64) ? 64 : 0);
        const float* izp  = (const float*)(smb + AT_SC(s) + 512);

#pragma unroll
        for (int g = 0; g < 4; g++) {
            // A = P[i, 16g..16g+15] = trans(E) * (scl*iz)
            uint32_t ef[4], af[4];
            ldsm4t(ef, esm + eat_off(16 * g, m0, lane));
            const int jb = 16 * g + 2 * (lane & 3);
            float sz0 = sclp[jb]     * izp[jb];
            float sz1 = sclp[jb + 1] * izp[jb + 1];
            float sz2 = sclp[jb + 8] * izp[jb + 8];
            float sz3 = sclp[jb + 9] * izp[jb + 9];
            __half2 zl = __floats2half2_rn(sz0, sz1);
            __half2 zh = __floats2half2_rn(sz2, sz3);
            __half2 a0 = __hmul2(*(__half2*)&ef[0], zl);
            __half2 a1 = __hmul2(*(__half2*)&ef[1], zl);
            __half2 a2 = __hmul2(*(__half2*)&ef[2], zh);
            __half2 a3 = __hmul2(*(__half2*)&ef[3], zh);
            af[0] = *(uint32_t*)&a0; af[1] = *(uint32_t*)&a1;
            af[2] = *(uint32_t*)&a2; af[3] = *(uint32_t*)&a3;

            // O += P x V^T for this j-slice (ks = g), 128 c rows
#pragma unroll
            for (int g2 = 0; g2 < 8; g2++) {
                const uint32_t bo = bo_b + g2 * (16 * SST * 2) + g * 32;
                uint32_t bv[4];
                ldsm4(bv, vv + bo);
                mma_fp(o[2*g2],   af, bv[0], bv[1]);
                mma_fp(o[2*g2+1], af, bv[2], bv[3]);
            }
        }
    }

    // ---- accumulate partial O into out[b][c][i0 + r]
    float* ob = out + (size_t)b * CH * NPIX + i0;
    const int r0 = m0 + (lane >> 2);
#pragma unroll
    for (int nt = 0; nt < 16; nt++) {
        const int c = ch * 128 + 8 * nt + 2 * (lane & 3);
        atomicAdd(&ob[(size_t)c * NPIX + r0],           o[nt][0]);
        atomicAdd(&ob[(size_t)(c + 1) * NPIX + r0],     o[nt][1]);
        atomicAdd(&ob[(size_t)c * NPIX + r0 + 8],       o[nt][2]);
        atomicAdd(&ob[(size_t)(c + 1) * NPIX + r0 + 8], o[nt][3]);
    }
}

// ===========================================================================
extern "C" void kernel_launch(void* const* d_in, const int* in_sizes, int n_in,
                              void* d_out, int out_size)
{
    const float* xq = (const float*)d_in[0];
    const float* xk = (const float*)d_in[1];
    const float* xv = (const float*)d_in[2];
    const float* Wq = (const float*)d_in[3];
    const float* bq = (const float*)d_in[4];
    const float* Wk = (const float*)d_in[5];
    const float* bk = (const float*)d_in[6];
    const float* Wv = (const float*)d_in[7];
    const float* bv = (const float*)d_in[8];
    float* out = (float*)d_out;

    __nv_bfloat16 *qh, *ql, *khp, *klp;
    __half *vp, *ep;
    float *sclp, *gzp;
    cudaGetSymbolAddress((void**)&qh, g_qh);
    cudaGetSymbolAddress((void**)&ql, g_ql);
    cudaGetSymbolAddress((void**)&khp, g_kh);
    cudaGetSymbolAddress((void**)&klp, g_kl);
    cudaGetSymbolAddress((void**)&vp, g_v);
    cudaGetSymbolAddress((void**)&ep, g_e);
    cudaGetSymbolAddress((void**)&sclp, g_scl);
    cudaGetSymbolAddress((void**)&gzp, g_z);

    cudaFuncSetAttribute(proj_all_mma, cudaFuncAttributeMaxDynamicSharedMemorySize, PSMEM);
    cudaFuncSetAttribute(rowstats_mma, cudaFuncAttributeMaxDynamicSharedMemorySize, RS_SMEM);
    cudaFuncSetAttribute(attn_mma,     cudaFuncAttributeMaxDynamicSharedMemorySize, AT_SMEM);

    dim3 blk(256);
    proj_all_mma<<<dim3(NPIX / 128, 6, BATCH), blk, PSMEM>>>(
        xq, xk, xv, Wq, Wk, Wv, bq, bk, bv, qh, ql, khp, klp, vp);

    rowstats_mma<<<dim3(NPIX / 128, BATCH), blk, RS_SMEM>>>(qh, ql, khp, klp, ep, sclp, gzp);

    zero_out_kernel<<<(BATCH * CH * NPIX / 4) / 1024, blk>>>((float4*)out);

    attn_mma<<<dim3(NPIX / 128, JSPLIT * 2, BATCH), blk, AT_SMEM>>>(ep, sclp, gzp, vp, out);
}